// round 17
// baseline (speedup 1.0000x reference)
#include <cuda_runtime.h>
#include <cuda_bf16.h>
#include <cuda_fp16.h>
#include <math.h>
#include <stdint.h>

// Problem dims (fixed)
#define BB   2
#define TT   2048
#define DD   2048
#define HH   16
#define HD   128
#define FF   4096
#define MTOK 4096            // B*T
#define QKVW (3*DD)          // 6144

#define NSM_CTAS 296         // 148 SMs x 2 CTAs (persistent GEMM grid)

// ---------------- scratch (static __device__, no allocations) ----------------
__device__ float g_x1  [(size_t)MTOK * DD];    // x after attention residual
__device__ __half g_gate[(size_t)MTOK * FF];   // gate proj (fp16)

// fp16 activation operand (h1 -> attn-out -> h2)
__device__ __half g_act [(size_t)MTOK * DD];
// fp16 qkv (QKV GEMM out); reused as ff buffer after attention
__device__ __half g_qkv [(size_t)MTOK * QKVW];

// weights: all single fp16 in ONE slab
#define W_QKV_OFF  0
#define W_O_OFF    ((size_t)QKVW * DD)
#define W_G_OFF    (W_O_OFF + (size_t)DD * DD)
#define W_U_OFF    (W_G_OFF + (size_t)FF * DD)
#define W_D_OFF    (W_U_OFF + (size_t)FF * DD)
#define W_TOTAL    (W_D_OFF + (size_t)DD * FF)
__device__ __half g_w[W_TOTAL];

// ======================= PTX helpers (baseline ISA only) =======================
__device__ __forceinline__ uint32_t smem_u32(const void* p) {
    uint32_t a;
    asm("{ .reg .u64 t; cvta.to.shared.u64 t, %1; cvt.u32.u64 %0, t; }" : "=r"(a) : "l"(p));
    return a;
}
__device__ __forceinline__ void cp_async16(uint32_t s, const void* g) {
    asm volatile("cp.async.cg.shared.global [%0], [%1], 16;" :: "r"(s), "l"(g));
}
__device__ __forceinline__ void cp_commit() { asm volatile("cp.async.commit_group;" ::: "memory"); }
#define CP_WAIT(n) asm volatile("cp.async.wait_group %0;" :: "n"(n) : "memory")

__device__ __forceinline__ void ldsm4(uint32_t* r, uint32_t addr) {
    asm volatile("ldmatrix.sync.aligned.m8n8.x4.shared.b16 {%0,%1,%2,%3}, [%4];"
        : "=r"(r[0]), "=r"(r[1]), "=r"(r[2]), "=r"(r[3]) : "r"(addr));
}
__device__ __forceinline__ void ldsm4t(uint32_t* r, uint32_t addr) {
    asm volatile("ldmatrix.sync.aligned.m8n8.x4.trans.shared.b16 {%0,%1,%2,%3}, [%4];"
        : "=r"(r[0]), "=r"(r[1]), "=r"(r[2]), "=r"(r[3]) : "r"(addr));
}
__device__ __forceinline__ void mma_f16(float* d, const uint32_t* a, const uint32_t* b) {
    asm volatile("mma.sync.aligned.m16n8k16.row.col.f32.f16.f16.f32 "
        "{%0,%1,%2,%3}, {%4,%5,%6,%7}, {%8,%9}, {%0,%1,%2,%3};"
        : "+f"(d[0]), "+f"(d[1]), "+f"(d[2]), "+f"(d[3])
        : "r"(a[0]), "r"(a[1]), "r"(a[2]), "r"(a[3]), "r"(b[0]), "r"(b[1]));
}

__device__ __forceinline__ uint32_t pack_h2(float a, float b) {
    __half2 h = __floats2half2_rn(a, b);
    return *(uint32_t*)&h;
}

// ---- ONE merged weight convert: 5 sources -> one fp16 slab ----
__global__ void __launch_bounds__(256) cvt_all_kernel(
    const float* __restrict__ s0, const float* __restrict__ s1,
    const float* __restrict__ s2, const float* __restrict__ s3,
    const float* __restrict__ s4, __half* __restrict__ out)
{
    const int n0 = QKVW * DD / 4;
    const int n1 = n0 + DD * DD / 4;
    const int n2 = n1 + FF * DD / 4;
    const int n3 = n2 + FF * DD / 4;
    const int n4 = n3 + DD * FF / 4;
    const int stride = gridDim.x * blockDim.x;
    for (int i = blockIdx.x * blockDim.x + threadIdx.x; i < n4; i += stride) {
        const float* src;
        int j;
        if (i < n0)      { src = s0; j = i; }
        else if (i < n1) { src = s1; j = i - n0; }
        else if (i < n2) { src = s2; j = i - n1; }
        else if (i < n3) { src = s3; j = i - n2; }
        else             { src = s4; j = i - n3; }
        float4 v = ((const float4*)src)[j];
        ((__half2*)out)[2 * (size_t)i]     = __floats2half2_rn(v.x, v.y);
        ((__half2*)out)[2 * (size_t)i + 1] = __floats2half2_rn(v.z, v.w);
    }
}

// ---------------- RMSNorm * w * gamma + beta -> fp16 ----------------
__global__ void __launch_bounds__(256) rmsnorm_affine_kernel(
    const float* __restrict__ x, const float* __restrict__ w,
    const float* __restrict__ gamma, const float* __restrict__ beta,
    __half* __restrict__ o)
{
    const int row = blockIdx.x;
    const float4* xr = (const float4*)(x + (size_t)row * DD);
    const int t = threadIdx.x;

    float4 v0 = xr[t];
    float4 v1 = xr[t + 256];
    float ss = v0.x*v0.x + v0.y*v0.y + v0.z*v0.z + v0.w*v0.w
             + v1.x*v1.x + v1.y*v1.y + v1.z*v1.z + v1.w*v1.w;
    #pragma unroll
    for (int d = 16; d; d >>= 1) ss += __shfl_xor_sync(0xffffffffu, ss, d);
    __shared__ float red[8];
    if ((t & 31) == 0) red[t >> 5] = ss;
    __syncthreads();
    float tot = red[0] + red[1] + red[2] + red[3] + red[4] + red[5] + red[6] + red[7];
    const float inv = rsqrtf(tot * (1.0f / DD) + 1.1920929e-07f);

    const float4* w4 = (const float4*)w;
    const float4* g4 = (const float4*)gamma;
    const float4* b4 = (const float4*)beta;
    __half2* orow = (__half2*)(o + (size_t)row * DD);
    #pragma unroll
    for (int c = 0; c < 2; ++c) {
        int i = t + c * 256;
        float4 xv = (c == 0) ? v0 : v1;
        float4 wv = w4[i], gv = g4[i], bv = b4[i];
        float4 r;
        r.x = xv.x * inv * wv.x * gv.x + bv.x;
        r.y = xv.y * inv * wv.y * gv.y + bv.y;
        r.z = xv.z * inv * wv.z * gv.z + bv.z;
        r.w = xv.w * inv * wv.w * gv.w + bv.w;
        orow[2 * i]     = __floats2half2_rn(r.x, r.y);
        orow[2 * i + 1] = __floats2half2_rn(r.z, r.w);
    }
}

// ======================= persistent mma.sync GEMM (fp16, 128x128 tile, occ 2) =======================
// C[M,N] = A[M,K] @ B[N,K]^T. CTA 128x128, BK=32, 8 warps (2Mx4N), warp 64x32.
// PERSISTENT: NSM_CTAS CTAs loop over tiles -> no wave-quantization tail.
// MODE: 1 = fp32 + res(fp32), 2 = fp16 out, 3 = silu(res16)*acc -> fp16 out
#define BKC 32
#define STG 4
#define STAGE_B 16384            // A 8K | B 8K
#define OFF_A 0
#define OFF_B 8192
#define GEMM_SMEM (STG * STAGE_B)   // 64 KB

// swizzled byte offset for (row, 16B-unit u) in a [rows][32]x16bit tile (64B rows)
#define SWZ(r_, u_) ((uint32_t)(r_) * 64u + ((((uint32_t)(u_)) ^ (((uint32_t)(r_) >> 1) & 3u)) << 4))

template<int MODE>
__global__ void __launch_bounds__(256, 2) gemm_mma_kernel(
    const __half* __restrict__ A, const __half* __restrict__ B,
    const float* __restrict__ res, float* __restrict__ C,
    __half* __restrict__ Ch, const __half* __restrict__ resh,
    int N, int K, int M)
{
    extern __shared__ char smraw[];
    const uint32_t sb = smem_u32(smraw);
    const int tid  = threadIdx.x;
    const int lane = tid & 31;
    const int warp = tid >> 5;
    const int wm = warp >> 2, wn = warp & 3;

    const int lr = tid >> 2, lu = tid & 3;
    const uint32_t wsw0 = SWZ(lr, lu);
    const uint32_t wsw1 = SWZ(lr + 64, lu);
    const size_t rK64 = (size_t)64 * K;
    const int nk = K / BKC;
    const int ntx = N >> 7;               // col tiles
    const int ntiles = (M >> 7) * ntx;

    const int m8 = lane >> 3;
    uint32_t offA[4][2], offB[2][2];
    #pragma unroll
    for (int i = 0; i < 4; ++i)
        #pragma unroll
        for (int kc = 0; kc < 2; ++kc) {
            int rowa = wm * 64 + i * 16 + ((m8 & 1) << 3) + (lane & 7);
            offA[i][kc] = SWZ(rowa, kc * 2 + (m8 >> 1));
        }
    #pragma unroll
    for (int nb = 0; nb < 2; ++nb)
        #pragma unroll
        for (int kc = 0; kc < 2; ++kc) {
            int rowb = wn * 32 + nb * 16 + ((m8 >> 1) << 3) + (lane & 7);
            offB[nb][kc] = SWZ(rowb, kc * 2 + (m8 & 1));
        }

    const int er = lane >> 2;
    const int ec = (lane & 3) * 2;

    for (int t = blockIdx.x; t < ntiles; t += gridDim.x) {
        const int row0 = (t / ntx) << 7;
        const int col0 = (t % ntx) << 7;
        const __half* gA = A + (size_t)(row0 + lr) * K + lu * 8;
        const __half* gB = B + (size_t)(col0 + lr) * K + lu * 8;

#define LOAD_STAGE(kt_, st_) do {                                   \
    uint32_t b_ = sb + (uint32_t)(st_) * STAGE_B;                   \
    size_t ko_ = (size_t)(kt_) * BKC;                               \
    cp_async16(b_ + OFF_A + wsw0, gA + ko_);                        \
    cp_async16(b_ + OFF_A + wsw1, gA + rK64 + ko_);                 \
    cp_async16(b_ + OFF_B + wsw0, gB + ko_);                        \
    cp_async16(b_ + OFF_B + wsw1, gB + rK64 + ko_);                 \
    cp_commit();                                                    \
} while (0)

        float acc[4][4][4];
        #pragma unroll
        for (int i = 0; i < 4; ++i)
            #pragma unroll
            for (int j = 0; j < 4; ++j)
                #pragma unroll
                for (int r = 0; r < 4; ++r) acc[i][j][r] = 0.f;

        __syncthreads();   // previous tile's smem readers done before overwrite
        LOAD_STAGE(0, 0);
        LOAD_STAGE(1, 1);
        LOAD_STAGE(2, 2);

        for (int kt = 0; kt < nk; ++kt) {
            const int rem = nk - 1 - kt;
            if (rem >= 2)      CP_WAIT(2);
            else if (rem == 1) CP_WAIT(1);
            else               CP_WAIT(0);
            __syncthreads();
            if (kt + 3 < nk) LOAD_STAGE(kt + 3, (kt + 3) & 3);

            const uint32_t base = sb + (uint32_t)(kt & 3) * STAGE_B;
            #pragma unroll
            for (int kc = 0; kc < 2; ++kc) {
                uint32_t ah[4][4];
                #pragma unroll
                for (int i = 0; i < 4; ++i)
                    ldsm4(ah[i], base + OFF_A + offA[i][kc]);
                #pragma unroll
                for (int nb = 0; nb < 2; ++nb) {
                    uint32_t bh[4];
                    ldsm4(bh, base + OFF_B + offB[nb][kc]);
                    #pragma unroll
                    for (int i = 0; i < 4; ++i) {
                        mma_f16(acc[i][nb * 2],     ah[i], bh);
                        mma_f16(acc[i][nb * 2 + 1], ah[i], bh + 2);
                    }
                }
            }
        }

        // ---- epilogue ----
        #pragma unroll
        for (int i = 0; i < 4; ++i) {
            const int grow = row0 + wm * 64 + i * 16 + er;
            #pragma unroll
            for (int jf = 0; jf < 4; ++jf) {
                const int gcol = col0 + wn * 32 + jf * 8 + ec;
                float v00 = acc[i][jf][0], v01 = acc[i][jf][1];
                float v10 = acc[i][jf][2], v11 = acc[i][jf][3];
                if (MODE == 1) {
                    float2 r0 = *(const float2*)(res + (size_t)grow * N + gcol);
                    float2 r1 = *(const float2*)(res + (size_t)(grow + 8) * N + gcol);
                    v00 += r0.x; v01 += r0.y; v10 += r1.x; v11 += r1.y;
                    *(float2*)(C + (size_t)grow * N + gcol) = make_float2(v00, v01);
                    *(float2*)(C + (size_t)(grow + 8) * N + gcol) = make_float2(v10, v11);
                } else {
                    if (MODE == 3) {
                        uint32_t u0 = *(const uint32_t*)(resh + (size_t)grow * N + gcol);
                        uint32_t u1 = *(const uint32_t*)(resh + (size_t)(grow + 8) * N + gcol);
                        float2 r0 = __half22float2(*(__half2*)&u0);
                        float2 r1 = __half22float2(*(__half2*)&u1);
                        v00 *= r0.x / (1.f + __expf(-r0.x));
                        v01 *= r0.y / (1.f + __expf(-r0.y));
                        v10 *= r1.x / (1.f + __expf(-r1.x));
                        v11 *= r1.y / (1.f + __expf(-r1.y));
                    }
                    *(uint32_t*)(Ch + (size_t)grow * N + gcol) = pack_h2(v00, v01);
                    *(uint32_t*)(Ch + (size_t)(grow + 8) * N + gcol) = pack_h2(v10, v11);
                }
            }
        }
#undef LOAD_STAGE
    }
}

// ======================= tensor-core causal flash attention (fp16, BC=128) =======================
// BR=128 (8 warps x m16), BC=128, HD=128. Heavy Q-tiles first.
// smem: Q 32K | 2 stages x (K 32K, V 32K) = 160KB.
#define ATT_SMEM 163840
// [128]fp16 rows = 256B = 16 units of 16B; swizzle u ^ (r&7)
#define SWA(r_, u_) ((uint32_t)(r_) * 256u + ((((uint32_t)(u_)) ^ ((uint32_t)(r_) & 7u)) << 4))

__global__ void __launch_bounds__(256) flash_attn_mma_kernel(
    const __half* __restrict__ qkv, __half* __restrict__ o)
{
    const int flat = blockIdx.x;
    const int qt = (TT / 128 - 1) - (flat >> 5);   // 15 .. 0 (heavy first)
    const int bh = flat & 31;
    const int b = bh >> 4, h = bh & 15;
    extern __shared__ char smraw[];
    const uint32_t sb = smem_u32(smraw);
    const uint32_t sQ = sb;

    const int tid = threadIdx.x;
    const int lane = tid & 31;
    const int w = tid >> 5;
    const int bT = b * TT;
    const int hO = h * HD;
    const float sc = 0.08838834764831845f;   // 1/sqrt(128)

    {
        const int r = tid >> 1, ub = (tid & 1) * 8;
        const __half* q_row = qkv + (size_t)(bT + qt * 128 + r) * QKVW + hO;
        #pragma unroll
        for (int i = 0; i < 8; ++i) {
            int u = ub + i;
            cp_async16(sQ + SWA(r, u), q_row + u * 8);
        }
    }
    const int kvr = tid >> 1, kvu = (tid & 1) * 8;
#define LOAD_KV(jt_, s_) do {                                                        \
    uint32_t bb_ = sb + 32768u + (uint32_t)(s_) * 65536u;                            \
    size_t tok_ = (size_t)(bT + (jt_) * 128 + kvr) * QKVW + hO;                      \
    _Pragma("unroll")                                                                \
    for (int i_ = 0; i_ < 8; ++i_) {                                                 \
        int u_ = kvu + i_;                                                           \
        uint32_t so_ = SWA(kvr, u_);                                                 \
        cp_async16(bb_ + so_,          qkv + tok_ + 2048 + u_ * 8);                  \
        cp_async16(bb_ + 32768u + so_, qkv + tok_ + 4096 + u_ * 8);                  \
    }                                                                                \
} while (0)

    LOAD_KV(0, 0);
    cp_commit();

    uint32_t offQ[8], offK[8], offV[8];
    {
        int rq = w * 16 + ((lane >> 3) & 1) * 8 + (lane & 7);
        #pragma unroll
        for (int c = 0; c < 8; ++c) offQ[c] = SWA(rq, 2 * c + (lane >> 4));
        int rk = ((lane >> 4) << 3) + (lane & 7);
        #pragma unroll
        for (int c = 0; c < 8; ++c) offK[c] = SWA(rk, 2 * c + ((lane >> 3) & 1));
        int rv = ((lane >> 3) & 1) * 8 + (lane & 7);
        #pragma unroll
        for (int hb = 0; hb < 8; ++hb) offV[hb] = SWA(rv, hb * 2 + (lane >> 4));
    }

    uint32_t qr[8][4];
    float Oa[16][4];
    #pragma unroll
    for (int g = 0; g < 16; ++g)
        #pragma unroll
        for (int r = 0; r < 4; ++r) Oa[g][r] = 0.f;
    float m0 = -INFINITY, m1 = -INFINITY, l0 = 0.f, l1 = 0.f;

    const int row0 = qt * 128 + w * 16 + (lane >> 2);
    const int row1 = row0 + 8;

    for (int jt = 0; jt <= qt; ++jt) {
        const int s = jt & 1;
        if (jt < qt) { LOAD_KV(jt + 1, s ^ 1); cp_commit(); CP_WAIT(1); }
        else         { CP_WAIT(0); }
        __syncthreads();

        if (jt == 0) {
            #pragma unroll
            for (int c = 0; c < 8; ++c) ldsm4(qr[c], sQ + offQ[c]);
        }

        const uint32_t bK = sb + 32768u + (uint32_t)s * 65536u;
        const uint32_t bV = bK + 32768u;

        float sf[16][4];
        #pragma unroll
        for (int i = 0; i < 16; ++i)
            #pragma unroll
            for (int r = 0; r < 4; ++r) sf[i][r] = 0.f;
        #pragma unroll
        for (int nb = 0; nb < 8; ++nb) {
            const uint32_t bKn = bK + (uint32_t)nb * 4096u;
            #pragma unroll
            for (int c = 0; c < 8; ++c) {
                uint32_t kh[4];
                ldsm4(kh, bKn + offK[c]);
                mma_f16(sf[nb * 2],     qr[c], kh);
                mma_f16(sf[nb * 2 + 1], qr[c], kh + 2);
            }
        }

        if (jt == qt) {
            const int jb = jt * 128 + (lane & 3) * 2;
            #pragma unroll
            for (int i = 0; i < 16; ++i) {
                int c0 = jb + i * 8;
                if (c0     > row0) sf[i][0] = -INFINITY;
                if (c0 + 1 > row0) sf[i][1] = -INFINITY;
                if (c0     > row1) sf[i][2] = -INFINITY;
                if (c0 + 1 > row1) sf[i][3] = -INFINITY;
            }
        }

        float mx0 = -INFINITY, mx1 = -INFINITY;
        #pragma unroll
        for (int i = 0; i < 16; ++i) {
            mx0 = fmaxf(mx0, fmaxf(sf[i][0], sf[i][1]));
            mx1 = fmaxf(mx1, fmaxf(sf[i][2], sf[i][3]));
        }
        mx0 *= sc; mx1 *= sc;
        mx0 = fmaxf(mx0, __shfl_xor_sync(0xffffffffu, mx0, 1));
        mx0 = fmaxf(mx0, __shfl_xor_sync(0xffffffffu, mx0, 2));
        mx1 = fmaxf(mx1, __shfl_xor_sync(0xffffffffu, mx1, 1));
        mx1 = fmaxf(mx1, __shfl_xor_sync(0xffffffffu, mx1, 2));
        float mn0 = fmaxf(m0, mx0), mn1 = fmaxf(m1, mx1);
        float al0 = __expf(m0 - mn0), al1 = __expf(m1 - mn1);
        m0 = mn0; m1 = mn1;
        float ps0 = 0.f, ps1 = 0.f;
        #pragma unroll
        for (int i = 0; i < 16; ++i) {
            sf[i][0] = __expf(fmaf(sf[i][0], sc, -m0)); ps0 += sf[i][0];
            sf[i][1] = __expf(fmaf(sf[i][1], sc, -m0)); ps0 += sf[i][1];
            sf[i][2] = __expf(fmaf(sf[i][2], sc, -m1)); ps1 += sf[i][2];
            sf[i][3] = __expf(fmaf(sf[i][3], sc, -m1)); ps1 += sf[i][3];
        }
        ps0 += __shfl_xor_sync(0xffffffffu, ps0, 1);
        ps0 += __shfl_xor_sync(0xffffffffu, ps0, 2);
        ps1 += __shfl_xor_sync(0xffffffffu, ps1, 1);
        ps1 += __shfl_xor_sync(0xffffffffu, ps1, 2);
        l0 = l0 * al0 + ps0; l1 = l1 * al1 + ps1;
        #pragma unroll
        for (int g = 0; g < 16; ++g) {
            Oa[g][0] *= al0; Oa[g][1] *= al0;
            Oa[g][2] *= al1; Oa[g][3] *= al1;
        }

        #pragma unroll
        for (int c2 = 0; c2 < 8; ++c2) {
            uint32_t ph[4];
            ph[0] = pack_h2(sf[2 * c2][0],     sf[2 * c2][1]);
            ph[1] = pack_h2(sf[2 * c2][2],     sf[2 * c2][3]);
            ph[2] = pack_h2(sf[2 * c2 + 1][0], sf[2 * c2 + 1][1]);
            ph[3] = pack_h2(sf[2 * c2 + 1][2], sf[2 * c2 + 1][3]);
            const uint32_t bVc = bV + (uint32_t)c2 * 4096u;
            #pragma unroll
            for (int hb = 0; hb < 8; ++hb) {
                uint32_t vh[4];
                ldsm4t(vh, bVc + offV[hb]);
                mma_f16(Oa[hb * 2],     ph, vh);
                mma_f16(Oa[hb * 2 + 1], ph, vh + 2);
            }
        }
        __syncthreads();
    }

    const float il0 = 1.0f / l0, il1 = 1.0f / l1;
    const size_t tok0 = (size_t)(bT + row0);
    #pragma unroll
    for (int g = 0; g < 16; ++g) {
        const int col = hO + g * 8 + (lane & 3) * 2;
        *(uint32_t*)(o + tok0 * DD + col) = pack_h2(Oa[g][0] * il0, Oa[g][1] * il0);
        *(uint32_t*)(o + (tok0 + 8) * DD + col) = pack_h2(Oa[g][2] * il1, Oa[g][3] * il1);
    }
#undef LOAD_KV
}

// ---------------- launch ----------------
extern "C" void kernel_launch(void* const* d_in, const int* in_sizes, int n_in,
                              void* d_out, int out_size)
{
    const float* x      = (const float*)d_in[0];
    const float* gamma  = (const float*)d_in[1];
    const float* beta   = (const float*)d_in[2];
    const float* qkv_w  = (const float*)d_in[3];
    const float* o_w    = (const float*)d_in[4];
    const float* gate_w = (const float*)d_in[5];
    const float* up_w   = (const float*)d_in[6];
    const float* down_w = (const float*)d_in[7];
    const float* n1w    = (const float*)d_in[8];
    const float* n2w    = (const float*)d_in[9];
    float* out = (float*)d_out;

    float *x1_;
    __half *gate_, *act_, *qkv_, *w_;
    cudaGetSymbolAddress((void**)&x1_,   g_x1);
    cudaGetSymbolAddress((void**)&gate_, g_gate);
    cudaGetSymbolAddress((void**)&act_,  g_act);
    cudaGetSymbolAddress((void**)&qkv_,  g_qkv);
    cudaGetSymbolAddress((void**)&w_,    g_w);
    __half* wq_ = w_ + W_QKV_OFF;
    __half* wo_ = w_ + W_O_OFF;
    __half* wg_ = w_ + W_G_OFF;
    __half* wu_ = w_ + W_U_OFF;
    __half* wd_ = w_ + W_D_OFF;

    cudaFuncSetAttribute(flash_attn_mma_kernel,
                         cudaFuncAttributeMaxDynamicSharedMemorySize, ATT_SMEM);
    cudaFuncSetAttribute(gemm_mma_kernel<1>,
                         cudaFuncAttributeMaxDynamicSharedMemorySize, GEMM_SMEM);
    cudaFuncSetAttribute(gemm_mma_kernel<2>,
                         cudaFuncAttributeMaxDynamicSharedMemorySize, GEMM_SMEM);
    cudaFuncSetAttribute(gemm_mma_kernel<3>,
                         cudaFuncAttributeMaxDynamicSharedMemorySize, GEMM_SMEM);

    // 0. all weights -> single fp16 slab, one launch
    cvt_all_kernel<<<2368, 256>>>(qkv_w, o_w, gate_w, up_w, down_w, w_);

    // 1. h = rmsnorm(x, n1)*gamma+beta -> act (fp16)
    rmsnorm_affine_kernel<<<MTOK, 256>>>(x, n1w, gamma, beta, act_);
    // 2. qkv = h @ qkv_w^T -> fp16  (persistent)
    gemm_mma_kernel<2><<<NSM_CTAS, 256, GEMM_SMEM>>>(
        act_, wq_, nullptr, nullptr, qkv_, nullptr, QKVW, DD, MTOK);
    // 3. attention (heavy tiles first) -> act (fp16)
    flash_attn_mma_kernel<<<(TT / 128) * BB * HH, 256, ATT_SMEM>>>(qkv_, act_);
    // 4. x1 = x + attn @ o_w^T
    gemm_mma_kernel<1><<<NSM_CTAS, 256, GEMM_SMEM>>>(
        act_, wo_, x, x1_, nullptr, nullptr, DD, DD, MTOK);
    // 5. h = rmsnorm(x1, n2)*gamma+beta -> act (fp16)
    rmsnorm_affine_kernel<<<MTOK, 256>>>(x1_, n2w, gamma, beta, act_);
    // 6. gate -> fp16
    gemm_mma_kernel<2><<<NSM_CTAS, 256, GEMM_SMEM>>>(
        act_, wg_, nullptr, nullptr, gate_, nullptr, FF, DD, MTOK);
    // 7. up with fused silu(gate)*up -> ff (fp16) into qkv buffer
    gemm_mma_kernel<3><<<NSM_CTAS, 256, GEMM_SMEM>>>(
        act_, wu_, nullptr, nullptr, qkv_, gate_, FF, DD, MTOK);
    // 8. out = x1 + ff @ down_w^T
    gemm_mma_kernel<1><<<NSM_CTAS, 256, GEMM_SMEM>>>(
        qkv_, wd_, x1_, out, nullptr, nullptr, DD, FF, MTOK);
}